// round 3
// baseline (speedup 1.0000x reference)
#include <cuda_runtime.h>
#include <math.h>

#define DIMD 128
#define PMAX 3136

// Scratch: diag(inv(b_covs[p]))[d], stored [D][P] for coalesced phase-B reads.
__device__ float g_dinv[DIMD * PMAX];

// ---------------------------------------------------------------------------
// Phase A: symmetric SWEEP operator. After sweeping all k, M = -inv(A).
// Symmetry is preserved every step, so only the lower triangle is maintained.
// TWO patches per CTA, packed into one 128x128 register square Q:
//   Q[i][j] = patchA[i][j]   (i >= j)   lower triangle incl. diagonal
//   Q[i][j] = patchB[j][i]   (i <  j)   patchB's lower triangle, mirrored
// patchB's diagonal lives in DB[8] on the 16 diagonal-tile threads.
//
// Thread->tile remap: diagonal tiles (t,t) -> tid 224..239 (all in warp 7),
// so role divergence is confined to a single warp.
//
// All register-tile indices are compile-time (templated step + unrolled
// loops) -- any runtime index demotes the tile to local memory.
// ---------------------------------------------------------------------------

template<int KNQ>
__device__ __forceinline__ void stage_col(
    const float (&T)[8][8], const float (&DB)[8],
    float* cAn, float* cBn,
    bool isDiag, int ty, int tx, int R0, int C0, int kkn)
{
    if (isDiag) {
        if (ty == kkn) {
#pragma unroll
            for (int a = 0; a < 8; a++) {
                if (a < KNQ)       { cBn[R0 + a] = T[a][KNQ];    cAn[R0 + a] = T[KNQ][a]; }
                else if (a == KNQ) { cAn[R0 + a] = T[KNQ][KNQ];  cBn[R0 + a] = DB[KNQ];   }
                else               { cAn[R0 + a] = T[a][KNQ];    cBn[R0 + a] = T[KNQ][a]; }
            }
        }
    } else {
        if (tx == kkn) {               // column-block tiles
            float* dst = (ty > kkn) ? cAn : cBn;
#pragma unroll
            for (int a = 0; a < 8; a++) dst[R0 + a] = T[a][KNQ];
        } else if (ty == kkn) {        // row-block tiles
            float* dst = (tx < kkn) ? cAn : cBn;
#pragma unroll
            for (int b = 0; b < 8; b++) dst[C0 + b] = T[KNQ][b];
        }
    }
}

template<int KQ>
__device__ __forceinline__ void sweep_step(
    float (&T)[8][8], float (&DB)[8],
    float (&cA)[2][DIMD], float (&cB)[2][DIMD],
    int kk, bool isDiag, bool low, int ty, int tx, int R0, int C0)
{
    constexpr int buf = KQ & 1;
    const int k = (kk << 3) + KQ;

    if (!isDiag) {
        // ---- uniform strict-tile path (lower = patchA, upper = patchB) ----
        const float* cX = low ? cA[buf] : cB[buf];
        float pv = 1.0f / cX[k];

        float rx[8], ry[8], sy[8];
        {
            const float4* xr = reinterpret_cast<const float4*>(cX + R0);
            float4 x0 = xr[0], x1 = xr[1];
            rx[0]=x0.x; rx[1]=x0.y; rx[2]=x0.z; rx[3]=x0.w;
            rx[4]=x1.x; rx[5]=x1.y; rx[6]=x1.z; rx[7]=x1.w;
            const float4* yr = reinterpret_cast<const float4*>(cX + C0);
            float4 y0 = yr[0], y1 = yr[1];
            ry[0]=y0.x; ry[1]=y0.y; ry[2]=y0.z; ry[3]=y0.w;
            ry[4]=y1.x; ry[5]=y1.y; ry[6]=y1.z; ry[7]=y1.w;
        }
#pragma unroll
        for (int b = 0; b < 8; b++) sy[b] = ry[b] * pv;

#pragma unroll
        for (int a = 0; a < 8; a++)
#pragma unroll
            for (int b = 0; b < 8; b++)
                T[a][b] = fmaf(-rx[a], sy[b], T[a][b]);

        // Fixups (derivation holds for both roles identically):
        if (kk == ty) {
#pragma unroll
            for (int b = 0; b < 8; b++) T[KQ][b] = sy[b];
        }
        if (kk == tx) {
#pragma unroll
            for (int a = 0; a < 8; a++) T[a][KQ] = rx[a] * pv;
        }
    } else {
        // ---- diagonal-tile path: patchA triangle + patchB triangle + DB ----
        float pvA = 1.0f / cA[buf][k];
        float pvB = 1.0f / cB[buf][k];

        float fa[8], sb[8], fb[8], sc[8];
        {
            const float4* ar = reinterpret_cast<const float4*>(&cA[buf][R0]);
            float4 a0 = ar[0], a1 = ar[1];
            fa[0]=a0.x; fa[1]=a0.y; fa[2]=a0.z; fa[3]=a0.w;
            fa[4]=a1.x; fa[5]=a1.y; fa[6]=a1.z; fa[7]=a1.w;
            const float4* br = reinterpret_cast<const float4*>(&cB[buf][R0]);
            float4 b0 = br[0], b1 = br[1];
            fb[0]=b0.x; fb[1]=b0.y; fb[2]=b0.z; fb[3]=b0.w;
            fb[4]=b1.x; fb[5]=b1.y; fb[6]=b1.z; fb[7]=b1.w;
        }
#pragma unroll
        for (int i = 0; i < 8; i++) { sb[i] = fa[i] * pvA; sc[i] = fb[i] * pvB; }

#pragma unroll
        for (int a = 0; a < 8; a++) {
#pragma unroll
            for (int b = 0; b < 8; b++) {
                if (b <= a) T[a][b] = fmaf(-fa[a], sb[b], T[a][b]);   // patchA
                else        T[a][b] = fmaf(-fb[b], sc[a], T[a][b]);   // patchB mirrored
            }
            DB[a] = fmaf(-fb[a], sc[a], DB[a]);                        // patchB diag
        }

        if (kk == ty) {   // pivot k lives inside this diagonal tile
#pragma unroll
            for (int b = 0; b < 8; b++) {
                if (b < KQ) {                 // patchA row-k fix
                    T[KQ][b] = sb[b];
                } else if (b > KQ) {          // patchB col-k fix
                    T[KQ][b] = sc[b];
                }
            }
#pragma unroll
            for (int a = 0; a < 8; a++) {
                if (a > KQ) {                 // patchA col-k fix
                    T[a][KQ] = sb[a];
                } else if (a < KQ) {          // patchB row-k fix
                    T[a][KQ] = sc[a];
                }
            }
            T[KQ][KQ] = -pvA;
            DB[KQ]    = -pvB;
        }
    }

    // Stage next pivot column (both patches) from the updated matrix.
    if (k < DIMD - 1) {
        constexpr int KNQ = (KQ + 1) & 7;
        int kkn = kk + ((KQ + 1) >> 3);
        stage_col<KNQ>(T, DB, cA[buf ^ 1], cB[buf ^ 1], isDiag, ty, tx, R0, C0, kkn);
    }
    __syncthreads();
}

__global__ __launch_bounds__(256, 1)
void sweep_diag_kernel(const float* __restrict__ covs, int P)
{
    int pA = blockIdx.x * 2;
    int pB = pA + 1;
    if (pB >= P) pB = pA;
    const float* MA = covs + (size_t)pA * DIMD * DIMD;
    const float* MB = covs + (size_t)pB * DIMD * DIMD;

    int tid = threadIdx.x;
    bool isDiag = (tid >= 224) && (tid < 240);
    int ty, tx;
    if (isDiag) {
        ty = tid - 224; tx = ty;
    } else {
        int s = (tid < 224) ? tid : (tid - 16);   // s in [0, 240)
        int r = s / 15;
        int c = s - r * 15;
        c += (c >= r) ? 1 : 0;                    // skip the diagonal
        ty = r; tx = c;
    }
    int R0 = ty << 3, C0 = tx << 3;
    bool low = (ty > tx);

    float T[8][8];
    float DB[8];

    // ---------------- load Q ----------------
    if (isDiag) {
#pragma unroll
        for (int a = 0; a < 8; a++) {
#pragma unroll
            for (int b = 0; b < 8; b++) {
                if (b <= a) T[a][b] = MA[(size_t)(R0 + a) * DIMD + (R0 + b)];
                else        T[a][b] = MB[(size_t)(R0 + b) * DIMD + (R0 + a)];
            }
            DB[a] = MB[(size_t)(R0 + a) * DIMD + (R0 + a)];
        }
    } else if (low) {
#pragma unroll
        for (int a = 0; a < 8; a++) {
            const float4* src = reinterpret_cast<const float4*>(MA + (size_t)(R0 + a) * DIMD + C0);
            float4 v0 = src[0], v1 = src[1];
            T[a][0]=v0.x; T[a][1]=v0.y; T[a][2]=v0.z; T[a][3]=v0.w;
            T[a][4]=v1.x; T[a][5]=v1.y; T[a][6]=v1.z; T[a][7]=v1.w;
        }
    } else {
        // upper tile: T[a][b] = Q[R0+a][C0+b] = MB[C0+b][R0+a]
#pragma unroll
        for (int b = 0; b < 8; b++) {
            const float4* src = reinterpret_cast<const float4*>(MB + (size_t)(C0 + b) * DIMD + R0);
            float4 v0 = src[0], v1 = src[1];
            T[0][b]=v0.x; T[1][b]=v0.y; T[2][b]=v0.z; T[3][b]=v0.w;
            T[4][b]=v1.x; T[5][b]=v1.y; T[6][b]=v1.z; T[7][b]=v1.w;
        }
#pragma unroll
        for (int a = 0; a < 8; a++) DB[a] = 0.0f;   // unused; keep defined
    }

    __shared__ float cA[2][DIMD];
    __shared__ float cB[2][DIMD];

    // Initial staging of pivot column 0 (both patches).
    stage_col<0>(T, DB, cA[0], cB[0], isDiag, ty, tx, R0, C0, 0);
    __syncthreads();

#pragma unroll 1
    for (int kk = 0; kk < 16; kk++) {
        sweep_step<0>(T, DB, cA, cB, kk, isDiag, low, ty, tx, R0, C0);
        sweep_step<1>(T, DB, cA, cB, kk, isDiag, low, ty, tx, R0, C0);
        sweep_step<2>(T, DB, cA, cB, kk, isDiag, low, ty, tx, R0, C0);
        sweep_step<3>(T, DB, cA, cB, kk, isDiag, low, ty, tx, R0, C0);
        sweep_step<4>(T, DB, cA, cB, kk, isDiag, low, ty, tx, R0, C0);
        sweep_step<5>(T, DB, cA, cB, kk, isDiag, low, ty, tx, R0, C0);
        sweep_step<6>(T, DB, cA, cB, kk, isDiag, low, ty, tx, R0, C0);
        sweep_step<7>(T, DB, cA, cB, kk, isDiag, low, ty, tx, R0, C0);
    }

    // After the full sweep, M = -inv(A): emit -diag.
    if (isDiag) {
#pragma unroll
        for (int a = 0; a < 8; a++) {
            g_dinv[(size_t)(R0 + a) * P + pA] = -T[a][a];
            g_dinv[(size_t)(R0 + a) * P + pB] = -DB[a];
        }
    }
}

// ---------------------------------------------------------------------------
// Phase B: streaming whitening + cosine similarity.
// 4 lanes cooperate per (b,p) output (32 d's each) + shfl reduction.
// ---------------------------------------------------------------------------
__global__ void ace_kernel(const float* __restrict__ X,
                           const float* __restrict__ bmean,
                           const float* __restrict__ covs,
                           const float* __restrict__ sig,
                           const int* __restrict__ covtype,
                           float* __restrict__ out,
                           int B, int P)
{
    int gtid = blockIdx.x * blockDim.x + threadIdx.x;
    int idx  = gtid >> 2;            // output index (b*P + p)
    int sub  = gtid & 3;             // which quarter of D this lane handles
    if (idx >= B * P) return;
    int b = idx / P;
    int p = idx - b * P;
    int ct = *covtype;

    float ww = 0.f, ws = 0.f, ss = 0.f;

    if (ct == 0) {
        // Full-covariance fallback: each lane does 32 of the 128 output dims.
        for (int m = sub * 32; m < sub * 32 + 32; m++) {
            float w = 0.f;
            const float* cr = covs + ((size_t)p * DIMD + m) * DIMD;
            for (int d = 0; d < DIMD; d++) {
                float xc = X[((size_t)b * DIMD + d) * P + p] - bmean[(size_t)d * P + p];
                w = fmaf(xc, cr[d], w);
            }
            float s = sig[(size_t)m * P + p];
            ww = fmaf(w, w, ww);
            ws = fmaf(w, s, ws);
            ss = fmaf(s, s, ss);
        }
    } else {
        bool use_diag = (ct == 1);
        int d0 = sub * 32;
#pragma unroll 16
        for (int i = 0; i < 32; i++) {
            int d = d0 + i;
            float xc = X[((size_t)b * DIMD + d) * P + p] - bmean[(size_t)d * P + p];
            float s  = sig[(size_t)d * P + p];
            float w  = use_diag ? (xc / g_dinv[(size_t)d * P + p]) : xc;
            ww = fmaf(w, w, ww);
            ws = fmaf(w, s, ws);
            ss = fmaf(s, s, ss);
        }
    }

#pragma unroll
    for (int m = 1; m < 4; m <<= 1) {
        ww += __shfl_xor_sync(0xFFFFFFFF, ww, m);
        ws += __shfl_xor_sync(0xFFFFFFFF, ws, m);
        ss += __shfl_xor_sync(0xFFFFFFFF, ss, m);
    }

    if (sub == 0) {
        float denom = fmaxf(sqrtf(ww), 1e-12f) * fmaxf(sqrtf(ss), 1e-12f);
        out[idx] = ws / denom;
    }
}

extern "C" void kernel_launch(void* const* d_in, const int* in_sizes, int n_in,
                              void* d_out, int out_size)
{
    const float* X      = (const float*)d_in[0];
    const float* bmean  = (const float*)d_in[1];
    const float* covs   = (const float*)d_in[2];
    const float* sig    = (const float*)d_in[3];
    const int*   ctype  = (const int*)d_in[4];
    float*       out    = (float*)d_out;

    int P = in_sizes[2] / (DIMD * DIMD);           // 3136
    int B = in_sizes[0] / (DIMD * P);              // 32

    sweep_diag_kernel<<<(P + 1) / 2, 256>>>(covs, P);

    int total = B * P * 4;                         // 4 lanes per output
    ace_kernel<<<(total + 255) / 256, 256>>>(X, bmean, covs, sig, ctype, out, B, P);
}

// round 4
// speedup vs baseline: 1.1592x; 1.1592x over previous
#include <cuda_runtime.h>
#include <math.h>

#define DIMD 128
#define PMAX 3136

// Scratch: diag(inv(b_covs[p]))[d], stored [D][P] for coalesced phase-B reads.
__device__ float g_dinv[DIMD * PMAX];

// ---------------------------------------------------------------------------
// Phase A: symmetric SWEEP operator on the lower triangle only.
// After sweeping all k:  M = -inv(A);  we emit -diag(M).
//
// Sweep step k (d = m_kk):
//   m_ij -= m_ik * m_jk / d   (i,j != k; note m_jk = m_kj by symmetry)
//   m_ik  = m_ik / d          (i != k)
//   m_kj  = m_kj / d          (j != k)
//   m_kk  = -1/d
//
// One CTA per patch. 288 threads; threads 0..271 each own a 4x8 register
// tile of the lower triangle (tile grid 32 row-blocks x 16 col-blocks;
// col-block c has row-blocks 2c..31 => 272 tiles). Straddle tiles carry a
// few mirrored upper entries which evolve correctly by symmetry.
//
// ONE staged column colv[k][0..127] (using symmetry for i<k) provides both
// multiplicands => single LDS buffer, uniform code for every lane.
//
// All register-tile indices are compile-time (unrolled loops); k appears
// only in comparisons and shared-memory addressing.
// ---------------------------------------------------------------------------
__global__ __launch_bounds__(288, 3)
void sweep_diag_kernel(const float* __restrict__ covs, int P)
{
    int p = blockIdx.x;
    const float* A = covs + (size_t)p * DIMD * DIMD;

    int tid = threadIdx.x;
    bool active = tid < 272;

    // tid -> (r, c): for c in 0..15, r in 2c..31 (32-2c tiles per col-block)
    int t = active ? tid : 0;
    int c = 0;
#pragma unroll 1
    while (t >= (32 - 2 * c)) { t -= (32 - 2 * c); c++; }
    int r = 2 * c + t;
    int R0 = r << 2;     // 4 rows
    int C0 = c << 3;     // 8 cols

    float T[4][8];
    if (active) {
#pragma unroll
        for (int a = 0; a < 4; a++) {
            const float4* src = reinterpret_cast<const float4*>(A + (size_t)(R0 + a) * DIMD + C0);
            float4 v0 = src[0], v1 = src[1];
            T[a][0]=v0.x; T[a][1]=v0.y; T[a][2]=v0.z; T[a][3]=v0.w;
            T[a][4]=v1.x; T[a][5]=v1.y; T[a][6]=v1.z; T[a][7]=v1.w;
        }
    }

    __shared__ float colv[2][DIMD];

    // Stage column 0: fully covered by col-block 0 tiles (i >= 0).
    if (active && c == 0) {
#pragma unroll
        for (int a = 0; a < 4; a++) colv[0][R0 + a] = T[a][0];
    }
    __syncthreads();

#pragma unroll 1
    for (int k = 0; k < DIMD; k++) {
        int buf = k & 1;

        if (active) {
            float pv = 1.0f / colv[buf][k];

            float ci[4], cj[8], sj[8];
            {
                const float4* xr = reinterpret_cast<const float4*>(&colv[buf][R0]);
                float4 x0 = xr[0];
                ci[0]=x0.x; ci[1]=x0.y; ci[2]=x0.z; ci[3]=x0.w;
                const float4* yr = reinterpret_cast<const float4*>(&colv[buf][C0]);
                float4 y0 = yr[0], y1 = yr[1];
                cj[0]=y0.x; cj[1]=y0.y; cj[2]=y0.z; cj[3]=y0.w;
                cj[4]=y1.x; cj[5]=y1.y; cj[6]=y1.z; cj[7]=y1.w;
            }
#pragma unroll
            for (int b = 0; b < 8; b++) sj[b] = cj[b] * pv;

            // Rank-1 update: 32 FFMA.
#pragma unroll
            for (int a = 0; a < 4; a++)
#pragma unroll
                for (int b = 0; b < 8; b++)
                    T[a][b] = fmaf(-ci[a], sj[b], T[a][b]);

            // Pivot-row fixup: m_kj = colv[j]/d.
            if ((k >> 2) == r) {
#pragma unroll
                for (int a = 0; a < 4; a++) {
                    if (R0 + a == k) {
#pragma unroll
                        for (int b = 0; b < 8; b++) T[a][b] = sj[b];
                    }
                }
            }
            // Pivot-col fixup: m_ik = colv[i]/d; m_kk = -1/d.
            if ((k >> 3) == c) {
#pragma unroll
                for (int b = 0; b < 8; b++) {
                    if (C0 + b == k) {
#pragma unroll
                        for (int a = 0; a < 4; a++)
                            T[a][b] = (R0 + a == k) ? -pv : ci[a] * pv;
                    }
                }
            }

            // Stage column k+1 from the UPDATED matrix into the other buffer.
            int kn = k + 1;
            if (kn < DIMD) {
                int nb = buf ^ 1;
                if ((kn >> 3) == c) {          // column entries: i >= kn
#pragma unroll
                    for (int b = 0; b < 8; b++) {
                        if (C0 + b == kn) {
#pragma unroll
                            for (int a = 0; a < 4; a++)
                                if (R0 + a >= kn) colv[nb][R0 + a] = T[a][b];
                        }
                    }
                }
                if ((kn >> 2) == r) {          // row entries (symmetry): j < kn
#pragma unroll
                    for (int a = 0; a < 4; a++) {
                        if (R0 + a == kn) {
#pragma unroll
                            for (int b = 0; b < 8; b++)
                                if (C0 + b < kn) colv[nb][C0 + b] = T[a][b];
                        }
                    }
                }
            }
        }
        __syncthreads();
    }

    // M = -inv(A); emit the diagonal. Diagonal elements live in tiles with
    // r == 2c or r == 2c+1.
    if (active && r <= 2 * c + 1) {
#pragma unroll
        for (int a = 0; a < 4; a++)
#pragma unroll
            for (int b = 0; b < 8; b++)
                if (R0 + a == C0 + b)
                    g_dinv[(size_t)(R0 + a) * P + p] = -T[a][b];
    }
}

// ---------------------------------------------------------------------------
// Phase B: streaming whitening + cosine similarity.
// 4 lanes cooperate per (b,p) output (32 d's each) + shfl reduction.
// ---------------------------------------------------------------------------
__global__ void ace_kernel(const float* __restrict__ X,
                           const float* __restrict__ bmean,
                           const float* __restrict__ covs,
                           const float* __restrict__ sig,
                           const int* __restrict__ covtype,
                           float* __restrict__ out,
                           int B, int P)
{
    int gtid = blockIdx.x * blockDim.x + threadIdx.x;
    int idx  = gtid >> 2;            // output index (b*P + p)
    int sub  = gtid & 3;             // which quarter of D this lane handles
    if (idx >= B * P) return;
    int b = idx / P;
    int p = idx - b * P;
    int ct = *covtype;

    float ww = 0.f, ws = 0.f, ss = 0.f;

    if (ct == 0) {
        // Full-covariance fallback: each lane does 32 of the 128 output dims.
        for (int m = sub * 32; m < sub * 32 + 32; m++) {
            float w = 0.f;
            const float* cr = covs + ((size_t)p * DIMD + m) * DIMD;
            for (int d = 0; d < DIMD; d++) {
                float xc = X[((size_t)b * DIMD + d) * P + p] - bmean[(size_t)d * P + p];
                w = fmaf(xc, cr[d], w);
            }
            float s = sig[(size_t)m * P + p];
            ww = fmaf(w, w, ww);
            ws = fmaf(w, s, ws);
            ss = fmaf(s, s, ss);
        }
    } else {
        bool use_diag = (ct == 1);
        int d0 = sub * 32;
#pragma unroll 16
        for (int i = 0; i < 32; i++) {
            int d = d0 + i;
            float xc = X[((size_t)b * DIMD + d) * P + p] - bmean[(size_t)d * P + p];
            float s  = sig[(size_t)d * P + p];
            float w  = use_diag ? (xc / g_dinv[(size_t)d * P + p]) : xc;
            ww = fmaf(w, w, ww);
            ws = fmaf(w, s, ws);
            ss = fmaf(s, s, ss);
        }
    }

#pragma unroll
    for (int m = 1; m < 4; m <<= 1) {
        ww += __shfl_xor_sync(0xFFFFFFFF, ww, m);
        ws += __shfl_xor_sync(0xFFFFFFFF, ws, m);
        ss += __shfl_xor_sync(0xFFFFFFFF, ss, m);
    }

    if (sub == 0) {
        float denom = fmaxf(sqrtf(ww), 1e-12f) * fmaxf(sqrtf(ss), 1e-12f);
        out[idx] = ws / denom;
    }
}

extern "C" void kernel_launch(void* const* d_in, const int* in_sizes, int n_in,
                              void* d_out, int out_size)
{
    const float* X      = (const float*)d_in[0];
    const float* bmean  = (const float*)d_in[1];
    const float* covs   = (const float*)d_in[2];
    const float* sig    = (const float*)d_in[3];
    const int*   ctype  = (const int*)d_in[4];
    float*       out    = (float*)d_out;

    int P = in_sizes[2] / (DIMD * DIMD);           // 3136
    int B = in_sizes[0] / (DIMD * P);              // 32

    sweep_diag_kernel<<<P, 288>>>(covs, P);

    int total = B * P * 4;                         // 4 lanes per output
    ace_kernel<<<(total + 255) / 256, 256>>>(X, bmean, covs, sig, ctype, out, B, P);
}